// round 11
// baseline (speedup 1.0000x reference)
#include <cuda_runtime.h>
#include <cstdint>

// ToRGB split-K conv + epilogue, R11.
// vs R10: TPB 512 (1 row x 4 px per thread) -> 8 warps/SMSP for latency hiding;
// ky-major weight layout (one LDS.128+LDS.64 per (co,ky)); 2 dummies so ncu
// (which captures global launch #3) lands on conv.

using ull = unsigned long long;

constexpr int TPB      = 512;
constexpr int HW       = 128;
constexpr int C_IN     = 512;
constexpr int C_PER    = 128;
constexpr int CPS      = 4;
constexpr int NSTAGE   = 2;
constexpr int NITER    = C_PER / CPS;                  // 32
constexpr int TILE_W   = 136;                          // idx = col + 4; zeros 0..3, 132..135
constexpr int TILE_ROWS= 18;                           // y0-1 .. y0+16
constexpr int TILE_FLOATS = TILE_ROWS * TILE_W;        // 2448
constexpr int CH_BYTES    = TILE_FLOATS * 4;           // 9792
constexpr int DATA_BYTES  = CPS * CH_BYTES;            // 39168
constexpr int WCH_ULL     = 36;                        // 3co x (3ky x 4 slots)
constexpr int WCH_BYTES   = WCH_ULL * 8;               // 288
constexpr int WSTAGE_BYTES= CPS * WCH_BYTES;           // 1152
constexpr int STAGE_BYTES = DATA_BYTES + WSTAGE_BYTES; // 40320
constexpr unsigned MBAR_OFF   = NSTAGE * STAGE_BYTES;  // 80640
constexpr unsigned SMEM_BYTES = MBAR_OFF + 64;

__device__ __align__(16) ull g_wdup[C_IN * WCH_ULL];
__device__ float g_part[4][8 * 3 * HW * HW];

__device__ __forceinline__ ull pack2(float lo, float hi) {
    ull r; asm("mov.b64 %0, {%1,%2};" : "=l"(r) : "f"(lo), "f"(hi)); return r;
}
__device__ __forceinline__ void unpack2(ull v, float& lo, float& hi) {
    asm("mov.b64 {%0,%1}, %2;" : "=f"(lo), "=f"(hi) : "l"(v));
}
__device__ __forceinline__ void ffma2(ull& d, ull a, ull b) {
    asm("fma.rn.f32x2 %0, %1, %2, %0;" : "+l"(d) : "l"(a), "l"(b));
}
__device__ __forceinline__ void bulk_cp(uint32_t dst, const void* src, uint32_t bytes,
                                        uint32_t mbar) {
    asm volatile("cp.async.bulk.shared::cluster.global.mbarrier::complete_tx::bytes "
                 "[%0], [%1], %2, [%3];"
                 :: "r"(dst), "l"(src), "r"(bytes), "r"(mbar) : "memory");
}
__device__ __forceinline__ void mbar_init(uint32_t mbar, uint32_t cnt) {
    asm volatile("mbarrier.init.shared.b64 [%0], %1;" :: "r"(mbar), "r"(cnt) : "memory");
}
__device__ __forceinline__ void mbar_expect_tx(uint32_t mbar, uint32_t bytes) {
    asm volatile("mbarrier.arrive.expect_tx.shared.b64 _, [%0], %1;"
                 :: "r"(mbar), "r"(bytes) : "memory");
}
__device__ __forceinline__ void mbar_wait(uint32_t mbar, uint32_t parity) {
    asm volatile(
        "{\n\t"
        ".reg .pred P;\n\t"
        "WAIT_%=:\n\t"
        "mbarrier.try_wait.parity.acquire.cta.shared::cta.b64 P, [%0], %1, 0x989680;\n\t"
        "@P bra.uni DONE_%=;\n\t"
        "bra.uni WAIT_%=;\n\t"
        "DONE_%=:\n\t"
        "}" :: "r"(mbar), "r"(parity) : "memory");
}

// ---------------- k0: weight prep ----------------
__global__ void prep_kernel(const float* __restrict__ weight)
{
    int i = blockIdx.x * 256 + threadIdx.x;
    if (i >= C_IN * WCH_ULL) return;
    int c = i / WCH_ULL, slot = i % WCH_ULL;
    int co = slot / 12, k2 = slot % 12;
    int ky = k2 >> 2, kx = k2 & 3;
    float w = 0.f;
    if (kx < 3)
        w = weight[(co * C_IN + c) * 9 + ky * 3 + kx] * (1.0f / sqrtf(4608.0f));
    g_wdup[i] = pack2(w, w);
}

// ---------------- dummy: shifts ncu capture (global launch #3) onto conv ------
__global__ void dummy_kernel() {}

// ---------------- k1: split-K conv ----------------
__global__ void __launch_bounds__(TPB, 2)
conv_kernel(const float* __restrict__ input)
{
    extern __shared__ char smem_raw[];
    float* tiles = reinterpret_cast<float*>(smem_raw);

    const int tid = threadIdx.x;
    const int tx4 = tid & 31;          // pixels 4*tx4 .. 4*tx4+3
    const int tyg = tid >> 5;          // 0..15: output row y0 + tyg
    const int b   = blockIdx.y;
    const int y0  = blockIdx.x * 16;
    const int qh  = blockIdx.z;
    const int cbase = qh * C_PER;

    uint32_t tiles_u32 = (uint32_t)__cvta_generic_to_shared(tiles);
    uint32_t mbar_u32  = tiles_u32 + MBAR_OFF;

    // zero the whole ring once (halo cols + OOB rows stay zero; bulk ops write
    // only bytes [16,528) of valid row slots)
    for (int i = tid; i < (int)(NSTAGE * STAGE_BYTES / 16); i += TPB)
        reinterpret_cast<float4*>(smem_raw)[i] = make_float4(0.f, 0.f, 0.f, 0.f);
    if (tid == 0) { mbar_init(mbar_u32, 1); mbar_init(mbar_u32 + 8, 1); }
    __syncthreads();

    const char* in_b = reinterpret_cast<const char*>(input) + (size_t)b * C_IN * HW * HW * 4;
    const char* wgl  = reinterpret_cast<const char*>(g_wdup);

    const int  vrows = TILE_ROWS - (y0 == 0 ? 1 : 0) - (y0 == 112 ? 1 : 0);
    const uint32_t stage_tx = (uint32_t)(CPS * vrows * 512 + WSTAGE_BYTES);

    const int my_ch  = tid / TILE_ROWS;
    const int my_row = tid - my_ch * TILE_ROWS;
    const int my_y   = y0 - 1 + my_row;
    const bool my_data = (tid < CPS * TILE_ROWS) && (my_y >= 0) && (my_y < HW);

    auto issue_stage = [&](int nc) {
        int s = nc & 1;
        uint32_t sb = tiles_u32 + s * STAGE_BYTES;
        uint32_t mb = mbar_u32 + s * 8;
        int bc = cbase + nc * CPS;
        if (tid == 0) mbar_expect_tx(mb, stage_tx);
        if (my_data)
            bulk_cp(sb + my_ch * CH_BYTES + my_row * (TILE_W * 4) + 16,
                    in_b + (size_t)(bc + my_ch) * (HW * HW * 4) + (size_t)my_y * (HW * 4),
                    512, mb);
        else if (tid == CPS * TILE_ROWS)
            bulk_cp(sb + DATA_BYTES, wgl + (size_t)bc * WCH_BYTES, WSTAGE_BYTES, mb);
    };

    issue_stage(0);
    issue_stage(1);

    ull acc[6];   // [co*2 + half]
#pragma unroll
    for (int i = 0; i < 6; i++) acc[i] = 0ull;

    for (int it = 0; it < NITER; it++) {
        mbar_wait(mbar_u32 + (it & 1) * 8, (it >> 1) & 1);

        const float* st = tiles + (it & 1) * (STAGE_BYTES / 4);
        const char*  wst = reinterpret_cast<const char*>(st) + DATA_BYTES;
#pragma unroll
        for (int ci = 0; ci < CPS; ci++) {
            const float* tp = st + ci * TILE_FLOATS + tyg * TILE_W;
            const char*  wc = wst + ci * WCH_BYTES;
#pragma unroll
            for (int r = 0; r < 3; r++) {   // input tile rows tyg..tyg+2 (= ky)
                const float* rp = tp + r * TILE_W;
                float s  = rp[4 * tx4 + 3];
                ulonglong2 cc = *reinterpret_cast<const ulonglong2*>(rp + 4 * tx4 + 4);
                float rr = rp[4 * tx4 + 8];
                float c0, c1, c2, c3;
                unpack2(cc.x, c0, c1);
                unpack2(cc.y, c2, c3);
                ull P0 = cc.x, P1 = cc.y;
                ull A0 = pack2(s,  c0);
                ull A1 = pack2(c1, c2);
                ull C1 = pack2(c3, rr);
#pragma unroll
                for (int co = 0; co < 3; co++) {
                    const char* wrow = wc + (co * 12 + r * 4) * 8;
                    ulonglong2 w01 = *reinterpret_cast<const ulonglong2*>(wrow);
                    ull        w2  = *reinterpret_cast<const ull*>(wrow + 16);
                    ffma2(acc[co * 2 + 0], w01.x, A0);
                    ffma2(acc[co * 2 + 1], w01.x, A1);
                    ffma2(acc[co * 2 + 0], w01.y, P0);
                    ffma2(acc[co * 2 + 1], w01.y, P1);
                    ffma2(acc[co * 2 + 0], w2,    A1);   // C0 == A1
                    ffma2(acc[co * 2 + 1], w2,    C1);
                }
            }
        }
        __syncthreads();                 // all warps done reading stage it&1
        if (it + 2 < NITER) issue_stage(it + 2);
    }

    {
        int y = y0 + tyg;
#pragma unroll
        for (int co = 0; co < 3; co++) {
            float l0, h0, l1, h1;
            unpack2(acc[co * 2 + 0], l0, h0);
            unpack2(acc[co * 2 + 1], l1, h1);
            float4 o; o.x = l0; o.y = h0; o.z = l1; o.w = h1;
            *reinterpret_cast<float4*>(
                &g_part[qh][(((size_t)(b * 3 + co) * HW + y) * HW) + 4 * tx4]) = o;
        }
    }
}

// ---------------- k2: epilogue ----------------
__global__ void __launch_bounds__(256)
epilogue_kernel(const float* __restrict__ skip, const float* __restrict__ bias,
                float* __restrict__ out)
{
    int id = blockIdx.x * 256 + threadIdx.x;
    int xp = id & 63;
    int y  = (id >> 6) & 127;
    int p  = id >> 13;
    int b  = p / 3, co = p % 3;

    float2 s = make_float2(0.f, 0.f);
#pragma unroll
    for (int h = 0; h < 4; h++) {
        float2 v = reinterpret_cast<const float2*>(g_part[h])[id];
        s.x += v.x; s.y += v.y;
    }
    float bs = bias[co];

    const float* sk = skip + ((size_t)b * 3 + co) * 64 * 64;
    int syn = y >> 1;
    int syf = (y & 1) ? syn + 1 : syn - 1;
    float wyf = (syf >= 0 && syf < 64) ? 0.25f : 0.0f;
    int syfc = min(63, max(0, syf));
    const float* rn = sk + syn * 64;
    const float* rf = sk + syfc * 64;
    float cl_n = (xp > 0)  ? rn[xp - 1] : 0.f;
    float cc_n = rn[xp];
    float cr_n = (xp < 63) ? rn[xp + 1] : 0.f;
    float cl_f = (xp > 0)  ? rf[xp - 1] : 0.f;
    float cc_f = rf[xp];
    float cr_f = (xp < 63) ? rf[xp + 1] : 0.f;
    float rnx0 = 0.75f * cc_n + 0.25f * cl_n;
    float rnx1 = 0.75f * cc_n + 0.25f * cr_n;
    float rfx0 = 0.75f * cc_f + 0.25f * cl_f;
    float rfx1 = 0.75f * cc_f + 0.25f * cr_f;
    float sx0 = 0.75f * rnx0 + wyf * rfx0;
    float sx1 = 0.75f * rnx1 + wyf * rfx1;

    float2 o;
    o.x = s.x + bs + sx0;
    o.y = s.y + bs + sx1;
    reinterpret_cast<float2*>(out)[id] = o;
}

extern "C" void kernel_launch(void* const* d_in, const int* in_sizes, int n_in,
                              void* d_out, int out_size)
{
    const float* input  = (const float*)d_in[0];
    const float* skip   = (const float*)d_in[1];
    const float* weight = (const float*)d_in[2];
    const float* bias   = (const float*)d_in[3];
    float* out = (float*)d_out;

    cudaFuncSetAttribute(conv_kernel,
                         cudaFuncAttributeMaxDynamicSharedMemorySize, SMEM_BYTES);

    prep_kernel<<<(C_IN * WCH_ULL + 255) / 256, 256>>>(weight);   // launch 0
    dummy_kernel<<<1, 1>>>();                                     // launch 1
    dummy_kernel<<<1, 1>>>();                                     // launch 2
    dim3 grid(8, 8, 4);
    conv_kernel<<<grid, TPB, SMEM_BYTES>>>(input);                // launch 3 (ncu)
    epilogue_kernel<<<(8 * 3 * HW * HW / 2) / 256, 256>>>(skip, bias, out);
}

// round 13
// speedup vs baseline: 1.2398x; 1.2398x over previous
#include <cuda_runtime.h>
#include <cstdint>

// ToRGB split-K conv + epilogue, R12.
// vs R11: 4-row register blocking (thread = 4 rows x 4 px) cuts LDS per output-channel
// from ~3.75 to ~2.0 (weights amortized over 4 rows; halo over 4 rows). L1 was the
// saturated pipe (76.4%). Tile 64x128, TPB 512, CPS=2, 8-way split-K, bulk-copy ring.

using ull = unsigned long long;

constexpr int TPB      = 512;
constexpr int HW       = 128;
constexpr int C_IN     = 512;
constexpr int C_PER    = 64;                           // channels per CTA (eighth)
constexpr int CPS      = 2;
constexpr int NSTAGE   = 2;
constexpr int NITER    = C_PER / CPS;                  // 32
constexpr int TILE_W   = 136;                          // idx = col + 4; zeros 0..3, 132..135
constexpr int TILE_ROWS= 66;                           // y0-1 .. y0+64
constexpr int TILE_FLOATS = TILE_ROWS * TILE_W;        // 8976
constexpr int CH_BYTES    = TILE_FLOATS * 4;           // 35904
constexpr int DATA_BYTES  = CPS * CH_BYTES;            // 71808
constexpr int WCH_ULL     = 28;                        // 27 weights + pad
constexpr int WCH_BYTES   = WCH_ULL * 8;               // 224
constexpr int WSTAGE_BYTES= CPS * WCH_BYTES;           // 448
constexpr int STAGE_BYTES = DATA_BYTES + WSTAGE_BYTES; // 72256
constexpr unsigned MBAR_OFF   = NSTAGE * STAGE_BYTES;  // 144512
constexpr unsigned SMEM_BYTES = MBAR_OFF + 64;

__device__ __align__(16) ull g_wdup[C_IN * WCH_ULL];
__device__ float g_part[8][8 * 3 * HW * HW];

__device__ __forceinline__ ull pack2(float lo, float hi) {
    ull r; asm("mov.b64 %0, {%1,%2};" : "=l"(r) : "f"(lo), "f"(hi)); return r;
}
__device__ __forceinline__ void unpack2(ull v, float& lo, float& hi) {
    asm("mov.b64 {%0,%1}, %2;" : "=f"(lo), "=f"(hi) : "l"(v));
}
__device__ __forceinline__ void ffma2(ull& d, ull a, ull b) {
    asm("fma.rn.f32x2 %0, %1, %2, %0;" : "+l"(d) : "l"(a), "l"(b));
}
__device__ __forceinline__ void bulk_cp(uint32_t dst, const void* src, uint32_t bytes,
                                        uint32_t mbar) {
    asm volatile("cp.async.bulk.shared::cluster.global.mbarrier::complete_tx::bytes "
                 "[%0], [%1], %2, [%3];"
                 :: "r"(dst), "l"(src), "r"(bytes), "r"(mbar) : "memory");
}
__device__ __forceinline__ void mbar_init(uint32_t mbar, uint32_t cnt) {
    asm volatile("mbarrier.init.shared.b64 [%0], %1;" :: "r"(mbar), "r"(cnt) : "memory");
}
__device__ __forceinline__ void mbar_expect_tx(uint32_t mbar, uint32_t bytes) {
    asm volatile("mbarrier.arrive.expect_tx.shared.b64 _, [%0], %1;"
                 :: "r"(mbar), "r"(bytes) : "memory");
}
__device__ __forceinline__ void mbar_wait(uint32_t mbar, uint32_t parity) {
    asm volatile(
        "{\n\t"
        ".reg .pred P;\n\t"
        "WAIT_%=:\n\t"
        "mbarrier.try_wait.parity.acquire.cta.shared::cta.b64 P, [%0], %1, 0x989680;\n\t"
        "@P bra.uni DONE_%=;\n\t"
        "bra.uni WAIT_%=;\n\t"
        "DONE_%=:\n\t"
        "}" :: "r"(mbar), "r"(parity) : "memory");
}

// ---------------- k0: weight prep ----------------
__global__ void prep_kernel(const float* __restrict__ weight)
{
    int i = blockIdx.x * 256 + threadIdx.x;
    if (i >= C_IN * WCH_ULL) return;
    int c = i / WCH_ULL, slot = i % WCH_ULL;
    int co = slot / 9, k = slot % 9;       // co==3 -> pad slot
    float w = 0.f;
    if (co < 3)
        w = weight[(co * C_IN + c) * 9 + k] * (1.0f / sqrtf(4608.0f));
    g_wdup[i] = pack2(w, w);
}

// ---------------- dummy: aligns ncu capture (global launch #3) onto conv ------
__global__ void dummy_kernel() {}

// ---------------- k1: split-K conv ----------------
__global__ void __launch_bounds__(TPB, 1)
conv_kernel(const float* __restrict__ input)
{
    extern __shared__ char smem_raw[];
    float* tiles = reinterpret_cast<float*>(smem_raw);

    const int tid = threadIdx.x;
    const int tx4 = tid & 31;          // pixels 4*tx4 .. 4*tx4+3
    const int tyg = tid >> 5;          // 0..15: output rows y0 + 4*tyg + {0..3}
    const int b   = blockIdx.y;
    const int y0  = blockIdx.x * 64;
    const int qh  = blockIdx.z;        // channel eighth
    const int cbase = qh * C_PER;

    uint32_t tiles_u32 = (uint32_t)__cvta_generic_to_shared(tiles);
    uint32_t mbar_u32  = tiles_u32 + MBAR_OFF;

    // zero whole ring once (halo cols + OOB rows stay zero; bulk writes only
    // bytes [16,528) of valid row slots)
    for (int i = tid; i < (int)(NSTAGE * STAGE_BYTES / 16); i += TPB)
        reinterpret_cast<float4*>(smem_raw)[i] = make_float4(0.f, 0.f, 0.f, 0.f);
    if (tid == 0) { mbar_init(mbar_u32, 1); mbar_init(mbar_u32 + 8, 1); }
    __syncthreads();

    const char* in_b = reinterpret_cast<const char*>(input) + (size_t)b * C_IN * HW * HW * 4;
    const char* wgl  = reinterpret_cast<const char*>(g_wdup);

    const int  vrows = TILE_ROWS - 1;                  // exactly one OOB row (bx=0: y-1, bx=1: y=128)
    const uint32_t stage_tx = (uint32_t)(CPS * vrows * 512 + WSTAGE_BYTES);

    const int my_ch  = tid / TILE_ROWS;                // valid for tid<132
    const int my_row = tid - my_ch * TILE_ROWS;
    const int my_y   = y0 - 1 + my_row;
    const bool my_data = (tid < CPS * TILE_ROWS) && (my_y >= 0) && (my_y < HW);

    auto issue_stage = [&](int nc) {
        int s = nc & 1;
        uint32_t sb = tiles_u32 + s * STAGE_BYTES;
        uint32_t mb = mbar_u32 + s * 8;
        int bc = cbase + nc * CPS;
        if (tid == 0) mbar_expect_tx(mb, stage_tx);
        if (my_data)
            bulk_cp(sb + my_ch * CH_BYTES + my_row * (TILE_W * 4) + 16,
                    in_b + (size_t)(bc + my_ch) * (HW * HW * 4) + (size_t)my_y * (HW * 4),
                    512, mb);
        else if (tid == CPS * TILE_ROWS)
            bulk_cp(sb + DATA_BYTES, wgl + (size_t)bc * WCH_BYTES, WSTAGE_BYTES, mb);
    };

    issue_stage(0);
    issue_stage(1);

    ull acc[24];   // [co][od][half] -> (co*4+od)*2 + h
#pragma unroll
    for (int i = 0; i < 24; i++) acc[i] = 0ull;

    const int trow0 = tyg * 4;
    for (int it = 0; it < NITER; it++) {
        mbar_wait(mbar_u32 + (it & 1) * 8, (it >> 1) & 1);

        const float* st  = tiles + (it & 1) * (STAGE_BYTES / 4);
        const char*  wst = reinterpret_cast<const char*>(st) + DATA_BYTES;
#pragma unroll
        for (int ci = 0; ci < CPS; ci++) {
            // all 27 weights for this channel into registers (14 LDS.128)
            ull w[28];
            {
                const ulonglong2* wp = reinterpret_cast<const ulonglong2*>(wst + ci * WCH_BYTES);
#pragma unroll
                for (int j = 0; j < 14; j++) {
                    ulonglong2 v = wp[j];
                    w[2 * j] = v.x; w[2 * j + 1] = v.y;
                }
            }
            const float* tp = st + ci * TILE_FLOATS + trow0 * TILE_W;
#pragma unroll
            for (int ir = 0; ir < 6; ir++) {       // input tile rows trow0..trow0+5
                const float* rp = tp + ir * TILE_W;
                float s  = rp[4 * tx4 + 3];
                ulonglong2 cc = *reinterpret_cast<const ulonglong2*>(rp + 4 * tx4 + 4);
                float rr = rp[4 * tx4 + 8];
                float c0, c1, c2, c3;
                unpack2(cc.x, c0, c1);
                unpack2(cc.y, c2, c3);
                ull P0 = cc.x, P1 = cc.y;
                ull A0 = pack2(s,  c0);
                ull A1 = pack2(c1, c2);
                ull C1 = pack2(c3, rr);
#pragma unroll
                for (int ky = 0; ky < 3; ky++) {
                    int od = ir - ky;
                    if (od < 0 || od > 3) continue;   // compile-time (ir,ky unrolled)
#pragma unroll
                    for (int co = 0; co < 3; co++) {
                        ull* a = &acc[(co * 4 + od) * 2];
                        const ull* wr = &w[co * 9 + ky * 3];
                        ffma2(a[0], wr[0], A0);
                        ffma2(a[1], wr[0], A1);
                        ffma2(a[0], wr[1], P0);
                        ffma2(a[1], wr[1], P1);
                        ffma2(a[0], wr[2], A1);   // C0 == A1
                        ffma2(a[1], wr[2], C1);
                    }
                }
            }
        }
        __syncthreads();                 // all warps done reading stage it&1
        if (it + 2 < NITER) issue_stage(it + 2);
    }

#pragma unroll
    for (int co = 0; co < 3; co++)
#pragma unroll
        for (int od = 0; od < 4; od++) {
            int y = y0 + tyg * 4 + od;
            float l0, h0, l1, h1;
            unpack2(acc[(co * 4 + od) * 2 + 0], l0, h0);
            unpack2(acc[(co * 4 + od) * 2 + 1], l1, h1);
            float4 o; o.x = l0; o.y = h0; o.z = l1; o.w = h1;
            *reinterpret_cast<float4*>(
                &g_part[qh][(((size_t)(b * 3 + co) * HW + y) * HW) + 4 * tx4]) = o;
        }
}

// ---------------- k2: epilogue ----------------
__global__ void __launch_bounds__(256)
epilogue_kernel(const float* __restrict__ skip, const float* __restrict__ bias,
                float* __restrict__ out)
{
    int id = blockIdx.x * 256 + threadIdx.x;
    int xp = id & 63;
    int y  = (id >> 6) & 127;
    int p  = id >> 13;
    int b  = p / 3, co = p % 3;

    float2 s = make_float2(0.f, 0.f);
#pragma unroll
    for (int h = 0; h < 8; h++) {
        float2 v = reinterpret_cast<const float2*>(g_part[h])[id];
        s.x += v.x; s.y += v.y;
    }
    float bs = bias[co];

    const float* sk = skip + ((size_t)b * 3 + co) * 64 * 64;
    int syn = y >> 1;
    int syf = (y & 1) ? syn + 1 : syn - 1;
    float wyf = (syf >= 0 && syf < 64) ? 0.25f : 0.0f;
    int syfc = min(63, max(0, syf));
    const float* rn = sk + syn * 64;
    const float* rf = sk + syfc * 64;
    float cl_n = (xp > 0)  ? rn[xp - 1] : 0.f;
    float cc_n = rn[xp];
    float cr_n = (xp < 63) ? rn[xp + 1] : 0.f;
    float cl_f = (xp > 0)  ? rf[xp - 1] : 0.f;
    float cc_f = rf[xp];
    float cr_f = (xp < 63) ? rf[xp + 1] : 0.f;
    float rnx0 = 0.75f * cc_n + 0.25f * cl_n;
    float rnx1 = 0.75f * cc_n + 0.25f * cr_n;
    float rfx0 = 0.75f * cc_f + 0.25f * cl_f;
    float rfx1 = 0.75f * cc_f + 0.25f * cr_f;
    float sx0 = 0.75f * rnx0 + wyf * rfx0;
    float sx1 = 0.75f * rnx1 + wyf * rfx1;

    float2 o;
    o.x = s.x + bs + sx0;
    o.y = s.y + bs + sx1;
    reinterpret_cast<float2*>(out)[id] = o;
}

extern "C" void kernel_launch(void* const* d_in, const int* in_sizes, int n_in,
                              void* d_out, int out_size)
{
    const float* input  = (const float*)d_in[0];
    const float* skip   = (const float*)d_in[1];
    const float* weight = (const float*)d_in[2];
    const float* bias   = (const float*)d_in[3];
    float* out = (float*)d_out;

    cudaFuncSetAttribute(conv_kernel,
                         cudaFuncAttributeMaxDynamicSharedMemorySize, SMEM_BYTES);

    prep_kernel<<<(C_IN * WCH_ULL + 255) / 256, 256>>>(weight);   // launch 0
    dummy_kernel<<<1, 1>>>();                                     // launch 1
    dummy_kernel<<<1, 1>>>();                                     // launch 2
    dim3 grid(2, 8, 8);
    conv_kernel<<<grid, TPB, SMEM_BYTES>>>(input);                // launch 3 (ncu)
    epilogue_kernel<<<(8 * 3 * HW * HW / 2) / 256, 256>>>(skip, bias, out);
}